// round 5
// baseline (speedup 1.0000x reference)
#include <cuda_runtime.h>
#include <cstdint>
#include <math.h>

// ---------------------------------------------------------------------------
// EZLSTM on GB300 (sm_103a)
//
// Structure:
//   g[gate][b][j] = x[:,0,:] @ W_gate + b_gate          (computed once, fp32)
//   repeat 512x:  z = h @ [uf|ui|uo|uc]  (tf32 mma.sync, fp32 accum)
//                 f,i,o = sigmoid(g+z), ch = tanh(g+z)
//                 c = f*c + i*ch ; h = o*tanh(c) ; out[:,t,:] = h
//
// 1 zero kernel + 1 init kernel + 512 step kernels, all captured in the graph.
// Scratch lives in __device__ globals (no allocation anywhere).
// ---------------------------------------------------------------------------

#define B_SZ 64
#define T_SZ 512
#define D_SZ 1024
#define H_SZ 1024

#define KC      32              // K-chunk per smem stage
#define NCHUNK  (H_SZ / KC)     // 32 chunks
#define A_STR   36              // smem stride for A tile (32x32), conflict-free
#define B_STR   72              // smem stride for B tile (32x64), conflict-free

// persistent scratch
__device__ float g_gates[4 * B_SZ * H_SZ];   // [gate][b][j]
__device__ float g_h[2][B_SZ * H_SZ];        // double-buffered hidden state
__device__ float g_c[B_SZ * H_SZ];           // cell state

__device__ __forceinline__ uint32_t f2tf32(float f) {
    // round-to-nearest tf32 conversion. RN (not truncation) is load-bearing:
    // truncation bias is coherent over K=1024 and would blow the 1e-3 budget.
    uint32_t r;
    asm("cvt.rna.tf32.f32 %0, %1;" : "=r"(r) : "f"(f));
    return r;
}

// ---------------------------------------------------------------------------
__global__ void lstm_zero_kernel() {
    int i = blockIdx.x * blockDim.x + threadIdx.x;
    if (i < B_SZ * H_SZ) {
        g_h[0][i] = 0.0f;
        g_c[i] = 0.0f;
    }
}

// ---------------------------------------------------------------------------
// g[gate] = x0 @ W_gate + b_gate, full fp32. One-time cost (~tens of us).
// grid: (H/256, B/8, 4), block: 256. Each thread: one j, 8 batch rows.
__global__ void lstm_init_gates(const float* __restrict__ x,
    const float* __restrict__ wf, const float* __restrict__ wi,
    const float* __restrict__ wo, const float* __restrict__ wc,
    const float* __restrict__ bf, const float* __restrict__ bi,
    const float* __restrict__ bo, const float* __restrict__ bc)
{
    const int gate = blockIdx.z;
    const int bg = blockIdx.y;                    // 8 batch rows per block
    const int j = blockIdx.x * blockDim.x + threadIdx.x;
    const float* w  = (gate == 0) ? wf : (gate == 1) ? wi : (gate == 2) ? wo : wc;
    const float* bb = (gate == 0) ? bf : (gate == 1) ? bi : (gate == 2) ? bo : bc;

    float acc[8];
    #pragma unroll
    for (int r = 0; r < 8; ++r) acc[r] = bb[j];

    for (int d = 0; d < D_SZ; ++d) {
        const float wv = w[d * H_SZ + j];         // coalesced across block
        #pragma unroll
        for (int r = 0; r < 8; ++r)
            acc[r] = fmaf(x[(bg * 8 + r) * (T_SZ * D_SZ) + d], wv, acc[r]);
    }
    #pragma unroll
    for (int r = 0; r < 8; ++r)
        g_gates[gate * (B_SZ * H_SZ) + (bg * 8 + r) * H_SZ + j] = acc[r];
}

// ---------------------------------------------------------------------------
// One recurrent step. grid = (64 n-groups, 2 m-tiles), block = 128 (4 warps).
// CTA tile: 32 batch rows x 16 hidden cols x all 4 gates (logical N = 64).
// Warp w owns gate w's 16 columns (warp tile m32 x n16 = 4 mma tiles/kstep).
// Double-buffered smem over K, register-staged prefetch issued before the
// barrier so L2 latency hides behind compute.
__global__ void __launch_bounds__(128) lstm_step_kernel(
    const float* __restrict__ uf, const float* __restrict__ ui,
    const float* __restrict__ uo, const float* __restrict__ uc,
    float* __restrict__ out, int t)
{
    __shared__ __align__(16) float sA[2 * 32 * A_STR];   // h tile (tf32 bits)
    __shared__ __align__(16) float sB[2 * KC * B_STR];   // U tile (tf32 bits)

    const int tid  = threadIdx.x;
    const int lane = tid & 31;
    const int wrp  = tid >> 5;
    const int jt   = blockIdx.x;          // 0..63  -> hidden cols jt*16..+15
    const int mb   = blockIdx.y;          // 0..1   -> batch rows mb*32..+31
    const int j0   = jt * 16;
    const int brow0 = mb * 32;

    const float* __restrict__ hsrc = g_h[t & 1];

    float acc[2][2][4];
    #pragma unroll
    for (int m = 0; m < 2; ++m)
        #pragma unroll
        for (int n = 0; n < 2; ++n)
            #pragma unroll
            for (int q = 0; q < 4; ++q) acc[m][n][q] = 0.0f;

    float4 ar[2];     // A stage: 32x32 floats = 256 float4 / 128 thr
    float4 br[4];     // B stage: 4 gates x 32x16 = 512 float4 / 128 thr

    auto load_regs = [&](int kc) {
        const int kbase = kc * KC;
        #pragma unroll
        for (int i = 0; i < 2; ++i) {
            const int flat = i * 128 + tid;
            const int row = flat >> 3;                // 0..31
            const int kv  = (flat & 7) << 2;          // 0..28 step 4
            ar[i] = *reinterpret_cast<const float4*>(
                &hsrc[(brow0 + row) * H_SZ + kbase + kv]);
        }
        const int row = tid >> 2;                     // 0..31
        const int nv  = (tid & 3) << 2;               // 0..12 step 4
        br[0] = *reinterpret_cast<const float4*>(&uf[(kbase + row) * H_SZ + j0 + nv]);
        br[1] = *reinterpret_cast<const float4*>(&ui[(kbase + row) * H_SZ + j0 + nv]);
        br[2] = *reinterpret_cast<const float4*>(&uo[(kbase + row) * H_SZ + j0 + nv]);
        br[3] = *reinterpret_cast<const float4*>(&uc[(kbase + row) * H_SZ + j0 + nv]);
    };

    auto cvt4 = [&](float4 v) -> float4 {
        float4 r;
        r.x = __uint_as_float(f2tf32(v.x));
        r.y = __uint_as_float(f2tf32(v.y));
        r.z = __uint_as_float(f2tf32(v.z));
        r.w = __uint_as_float(f2tf32(v.w));
        return r;
    };

    auto store_smem = [&](int buf) {
        float* A  = sA + buf * (32 * A_STR);
        float* Bv = sB + buf * (KC * B_STR);
        #pragma unroll
        for (int i = 0; i < 2; ++i) {
            const int flat = i * 128 + tid;
            const int row = flat >> 3;
            const int kv  = (flat & 7) << 2;
            *reinterpret_cast<float4*>(&A[row * A_STR + kv]) = cvt4(ar[i]);
        }
        const int row = tid >> 2;
        const int nv  = (tid & 3) << 2;
        #pragma unroll
        for (int g = 0; g < 4; ++g)
            *reinterpret_cast<float4*>(&Bv[row * B_STR + g * 16 + nv]) = cvt4(br[g]);
    };

    auto compute = [&](int buf) {
        const float* A  = sA + buf * (32 * A_STR);
        const float* Bv = sB + buf * (KC * B_STR);
        const int r  = lane >> 2;
        const int kq = lane & 3;
        #pragma unroll
        for (int ks = 0; ks < KC / 8; ++ks) {
            const int k0 = ks * 8;
            uint32_t af[2][4];
            #pragma unroll
            for (int mt = 0; mt < 2; ++mt) {
                af[mt][0] = __float_as_uint(A[(mt * 16 + r)     * A_STR + k0 + kq]);
                af[mt][1] = __float_as_uint(A[(mt * 16 + r + 8) * A_STR + k0 + kq]);
                af[mt][2] = __float_as_uint(A[(mt * 16 + r)     * A_STR + k0 + kq + 4]);
                af[mt][3] = __float_as_uint(A[(mt * 16 + r + 8) * A_STR + k0 + kq + 4]);
            }
            uint32_t bfr[2][2];
            #pragma unroll
            for (int nt = 0; nt < 2; ++nt) {
                const int cb = wrp * 16 + nt * 8 + r;
                bfr[nt][0] = __float_as_uint(Bv[(k0 + kq)     * B_STR + cb]);
                bfr[nt][1] = __float_as_uint(Bv[(k0 + kq + 4) * B_STR + cb]);
            }
            #pragma unroll
            for (int mt = 0; mt < 2; ++mt)
                #pragma unroll
                for (int nt = 0; nt < 2; ++nt) {
                    asm volatile(
                        "mma.sync.aligned.m16n8k8.row.col.f32.tf32.tf32.f32 "
                        "{%0,%1,%2,%3},{%4,%5,%6,%7},{%8,%9},{%0,%1,%2,%3};\n"
                        : "+f"(acc[mt][nt][0]), "+f"(acc[mt][nt][1]),
                          "+f"(acc[mt][nt][2]), "+f"(acc[mt][nt][3])
                        : "r"(af[mt][0]), "r"(af[mt][1]),
                          "r"(af[mt][2]), "r"(af[mt][3]),
                          "r"(bfr[nt][0]), "r"(bfr[nt][1]));
                }
        }
    };

    // --- K mainloop: prefetch kc+1 issued BEFORE the barrier so the L2
    // latency overlaps the barrier wait + compute of chunk kc.
    load_regs(0);
    store_smem(0);
    for (int kc = 0; kc < NCHUNK; ++kc) {
        if (kc + 1 < NCHUNK) load_regs(kc + 1);
        __syncthreads();
        compute(kc & 1);
        if (kc + 1 < NCHUNK) store_smem((kc + 1) & 1);
    }
    __syncthreads();

    // --- Stage z into smem (alias over sB buf0: 32*68*4 = 8704B <= 9216B)
    // so the gate epilogue can read all 4 gates for a given (b, j).
    float* Z = sB;
    {
        const int r  = lane >> 2;
        const int cq = (lane & 3) * 2;
        #pragma unroll
        for (int mt = 0; mt < 2; ++mt)
            #pragma unroll
            for (int nt = 0; nt < 2; ++nt) {
                const int rr = mt * 16 + r;
                const int cc = wrp * 16 + nt * 8 + cq;
                Z[rr * 68 + cc]           = acc[mt][nt][0];
                Z[rr * 68 + cc + 1]       = acc[mt][nt][1];
                Z[(rr + 8) * 68 + cc]     = acc[mt][nt][2];
                Z[(rr + 8) * 68 + cc + 1] = acc[mt][nt][3];
            }
    }
    __syncthreads();

    // --- Gate math + state update + output write. 512 outputs / 128 threads.
    float* __restrict__ hdst = g_h[(t + 1) & 1];
    #pragma unroll
    for (int i = 0; i < 4; ++i) {
        const int flat = i * 128 + tid;
        const int row = flat >> 4;          // 0..31
        const int jj  = flat & 15;          // 0..15
        const int b = brow0 + row;
        const int j = j0 + jj;
        const int bj = b * H_SZ + j;
        const float zf = Z[row * 68 + jj]      + g_gates[0 * (B_SZ * H_SZ) + bj];
        const float zi = Z[row * 68 + 16 + jj] + g_gates[1 * (B_SZ * H_SZ) + bj];
        const float zo = Z[row * 68 + 32 + jj] + g_gates[2 * (B_SZ * H_SZ) + bj];
        const float zc = Z[row * 68 + 48 + jj] + g_gates[3 * (B_SZ * H_SZ) + bj];
        const float fg = 1.0f / (1.0f + expf(-zf));
        const float ig = 1.0f / (1.0f + expf(-zi));
        const float og = 1.0f / (1.0f + expf(-zo));
        const float ch = tanhf(zc);
        const float cn = fg * g_c[bj] + ig * ch;
        const float hn = og * tanhf(cn);
        g_c[bj] = cn;
        hdst[bj] = hn;
        out[(b * T_SZ + t) * H_SZ + j] = hn;
    }
}

// ---------------------------------------------------------------------------
extern "C" void kernel_launch(void* const* d_in, const int* in_sizes, int n_in,
                              void* d_out, int out_size) {
    (void)in_sizes; (void)n_in; (void)out_size;
    const float* x  = (const float*)d_in[0];
    const float* wf = (const float*)d_in[1];
    const float* wi = (const float*)d_in[2];
    const float* wo = (const float*)d_in[3];
    const float* wc = (const float*)d_in[4];
    const float* uf = (const float*)d_in[5];
    const float* ui = (const float*)d_in[6];
    const float* uo = (const float*)d_in[7];
    const float* uc = (const float*)d_in[8];
    const float* bf = (const float*)d_in[9];
    const float* bi = (const float*)d_in[10];
    const float* bo = (const float*)d_in[11];
    const float* bc = (const float*)d_in[12];
    float* out = (float*)d_out;

    lstm_zero_kernel<<<(B_SZ * H_SZ + 255) / 256, 256>>>();
    lstm_init_gates<<<dim3(H_SZ / 256, B_SZ / 8, 4), 256>>>(
        x, wf, wi, wo, wc, bf, bi, bo, bc);
    for (int t = 0; t < T_SZ; ++t) {
        lstm_step_kernel<<<dim3(H_SZ / 16, 2), 128>>>(uf, ui, uo, uc, out, t);
    }
}

// round 6
// speedup vs baseline: 1.0077x; 1.0077x over previous
#include <cuda_runtime.h>
#include <cstdint>
#include <math.h>

// ---------------------------------------------------------------------------
// EZLSTM on GB300 (sm_103a)
//
// Structure:
//   g[gate][b][j] = x[:,0,:] @ W_gate + b_gate          (computed once, fp32)
//   repeat 512x:  z = h @ [uf|ui|uo|uc]  (tf32 mma.sync, fp32 accum)
//                 f,i,o = sigmoid(g+z), ch = tanh(g+z)
//                 c = f*c + i*ch ; h = o*tanh(c) ; out[:,t,:] = h
//
// 1 zero kernel + 1 init kernel + 512 step kernels, all captured in the graph.
// Scratch lives in __device__ globals (no allocation anywhere).
// ---------------------------------------------------------------------------

#define B_SZ 64
#define T_SZ 512
#define D_SZ 1024
#define H_SZ 1024

#define KC      32              // K-chunk per smem stage
#define NCHUNK  (H_SZ / KC)     // 32 chunks
#define A_STR   36              // smem stride for A tile (32x32), conflict-free
#define B_STR   72              // smem stride for B tile (32x64), conflict-free

// persistent scratch
__device__ float g_gates[4 * B_SZ * H_SZ];   // [gate][b][j]
__device__ float g_h[2][B_SZ * H_SZ];        // double-buffered hidden state
__device__ float g_c[B_SZ * H_SZ];           // cell state

__device__ __forceinline__ uint32_t f2tf32(float f) {
    // round-to-nearest tf32 conversion. RN (not truncation) is load-bearing:
    // truncation bias is coherent over K=1024 and would blow the 1e-3 budget.
    uint32_t r;
    asm("cvt.rna.tf32.f32 %0, %1;" : "=r"(r) : "f"(f));
    return r;
}

// ---------------------------------------------------------------------------
__global__ void lstm_zero_kernel() {
    int i = blockIdx.x * blockDim.x + threadIdx.x;
    if (i < B_SZ * H_SZ) {
        g_h[0][i] = 0.0f;
        g_c[i] = 0.0f;
    }
}

// ---------------------------------------------------------------------------
// g[gate] = x0 @ W_gate + b_gate, full fp32. One-time cost (~tens of us).
// grid: (H/256, B/8, 4), block: 256. Each thread: one j, 8 batch rows.
__global__ void lstm_init_gates(const float* __restrict__ x,
    const float* __restrict__ wf, const float* __restrict__ wi,
    const float* __restrict__ wo, const float* __restrict__ wc,
    const float* __restrict__ bf, const float* __restrict__ bi,
    const float* __restrict__ bo, const float* __restrict__ bc)
{
    const int gate = blockIdx.z;
    const int bg = blockIdx.y;                    // 8 batch rows per block
    const int j = blockIdx.x * blockDim.x + threadIdx.x;
    const float* w  = (gate == 0) ? wf : (gate == 1) ? wi : (gate == 2) ? wo : wc;
    const float* bb = (gate == 0) ? bf : (gate == 1) ? bi : (gate == 2) ? bo : bc;

    float acc[8];
    #pragma unroll
    for (int r = 0; r < 8; ++r) acc[r] = bb[j];

    for (int d = 0; d < D_SZ; ++d) {
        const float wv = w[d * H_SZ + j];         // coalesced across block
        #pragma unroll
        for (int r = 0; r < 8; ++r)
            acc[r] = fmaf(x[(bg * 8 + r) * (T_SZ * D_SZ) + d], wv, acc[r]);
    }
    #pragma unroll
    for (int r = 0; r < 8; ++r)
        g_gates[gate * (B_SZ * H_SZ) + (bg * 8 + r) * H_SZ + j] = acc[r];
}

// ---------------------------------------------------------------------------
// One recurrent step. grid = (64 n-groups, 2 m-tiles), block = 128 (4 warps).
// CTA tile: 32 batch rows x 16 hidden cols x all 4 gates (logical N = 64).
// Warp w owns gate w's 16 columns (warp tile m32 x n16 = 4 mma tiles/kstep).
// Double-buffered smem over K, register-staged prefetch issued before the
// barrier so L2 latency hides behind compute.
__global__ void __launch_bounds__(128) lstm_step_kernel(
    const float* __restrict__ uf, const float* __restrict__ ui,
    const float* __restrict__ uo, const float* __restrict__ uc,
    float* __restrict__ out, int t)
{
    __shared__ __align__(16) float sA[2 * 32 * A_STR];   // h tile (tf32 bits)
    __shared__ __align__(16) float sB[2 * KC * B_STR];   // U tile (tf32 bits)

    const int tid  = threadIdx.x;
    const int lane = tid & 31;
    const int wrp  = tid >> 5;
    const int jt   = blockIdx.x;          // 0..63  -> hidden cols jt*16..+15
    const int mb   = blockIdx.y;          // 0..1   -> batch rows mb*32..+31
    const int j0   = jt * 16;
    const int brow0 = mb * 32;

    const float* __restrict__ hsrc = g_h[t & 1];

    float acc[2][2][4];
    #pragma unroll
    for (int m = 0; m < 2; ++m)
        #pragma unroll
        for (int n = 0; n < 2; ++n)
            #pragma unroll
            for (int q = 0; q < 4; ++q) acc[m][n][q] = 0.0f;

    float4 ar[2];     // A stage: 32x32 floats = 256 float4 / 128 thr
    float4 br[4];     // B stage: 4 gates x 32x16 = 512 float4 / 128 thr

    auto load_regs = [&](int kc) {
        const int kbase = kc * KC;
        #pragma unroll
        for (int i = 0; i < 2; ++i) {
            const int flat = i * 128 + tid;
            const int row = flat >> 3;                // 0..31
            const int kv  = (flat & 7) << 2;          // 0..28 step 4
            ar[i] = *reinterpret_cast<const float4*>(
                &hsrc[(brow0 + row) * H_SZ + kbase + kv]);
        }
        const int row = tid >> 2;                     // 0..31
        const int nv  = (tid & 3) << 2;               // 0..12 step 4
        br[0] = *reinterpret_cast<const float4*>(&uf[(kbase + row) * H_SZ + j0 + nv]);
        br[1] = *reinterpret_cast<const float4*>(&ui[(kbase + row) * H_SZ + j0 + nv]);
        br[2] = *reinterpret_cast<const float4*>(&uo[(kbase + row) * H_SZ + j0 + nv]);
        br[3] = *reinterpret_cast<const float4*>(&uc[(kbase + row) * H_SZ + j0 + nv]);
    };

    auto cvt4 = [&](float4 v) -> float4 {
        float4 r;
        r.x = __uint_as_float(f2tf32(v.x));
        r.y = __uint_as_float(f2tf32(v.y));
        r.z = __uint_as_float(f2tf32(v.z));
        r.w = __uint_as_float(f2tf32(v.w));
        return r;
    };

    auto store_smem = [&](int buf) {
        float* A  = sA + buf * (32 * A_STR);
        float* Bv = sB + buf * (KC * B_STR);
        #pragma unroll
        for (int i = 0; i < 2; ++i) {
            const int flat = i * 128 + tid;
            const int row = flat >> 3;
            const int kv  = (flat & 7) << 2;
            *reinterpret_cast<float4*>(&A[row * A_STR + kv]) = cvt4(ar[i]);
        }
        const int row = tid >> 2;
        const int nv  = (tid & 3) << 2;
        #pragma unroll
        for (int g = 0; g < 4; ++g)
            *reinterpret_cast<float4*>(&Bv[row * B_STR + g * 16 + nv]) = cvt4(br[g]);
    };

    auto compute = [&](int buf) {
        const float* A  = sA + buf * (32 * A_STR);
        const float* Bv = sB + buf * (KC * B_STR);
        const int r  = lane >> 2;
        const int kq = lane & 3;
        #pragma unroll
        for (int ks = 0; ks < KC / 8; ++ks) {
            const int k0 = ks * 8;
            uint32_t af[2][4];
            #pragma unroll
            for (int mt = 0; mt < 2; ++mt) {
                af[mt][0] = __float_as_uint(A[(mt * 16 + r)     * A_STR + k0 + kq]);
                af[mt][1] = __float_as_uint(A[(mt * 16 + r + 8) * A_STR + k0 + kq]);
                af[mt][2] = __float_as_uint(A[(mt * 16 + r)     * A_STR + k0 + kq + 4]);
                af[mt][3] = __float_as_uint(A[(mt * 16 + r + 8) * A_STR + k0 + kq + 4]);
            }
            uint32_t bfr[2][2];
            #pragma unroll
            for (int nt = 0; nt < 2; ++nt) {
                const int cb = wrp * 16 + nt * 8 + r;
                bfr[nt][0] = __float_as_uint(Bv[(k0 + kq)     * B_STR + cb]);
                bfr[nt][1] = __float_as_uint(Bv[(k0 + kq + 4) * B_STR + cb]);
            }
            #pragma unroll
            for (int mt = 0; mt < 2; ++mt)
                #pragma unroll
                for (int nt = 0; nt < 2; ++nt) {
                    asm volatile(
                        "mma.sync.aligned.m16n8k8.row.col.f32.tf32.tf32.f32 "
                        "{%0,%1,%2,%3},{%4,%5,%6,%7},{%8,%9},{%0,%1,%2,%3};\n"
                        : "+f"(acc[mt][nt][0]), "+f"(acc[mt][nt][1]),
                          "+f"(acc[mt][nt][2]), "+f"(acc[mt][nt][3])
                        : "r"(af[mt][0]), "r"(af[mt][1]),
                          "r"(af[mt][2]), "r"(af[mt][3]),
                          "r"(bfr[nt][0]), "r"(bfr[nt][1]));
                }
        }
    };

    // --- K mainloop: prefetch kc+1 issued BEFORE the barrier so the L2
    // latency overlaps the barrier wait + compute of chunk kc.
    load_regs(0);
    store_smem(0);
    for (int kc = 0; kc < NCHUNK; ++kc) {
        if (kc + 1 < NCHUNK) load_regs(kc + 1);
        __syncthreads();
        compute(kc & 1);
        if (kc + 1 < NCHUNK) store_smem((kc + 1) & 1);
    }
    __syncthreads();

    // --- Stage z into smem (alias over sB buf0: 32*68*4 = 8704B <= 9216B)
    // so the gate epilogue can read all 4 gates for a given (b, j).
    float* Z = sB;
    {
        const int r  = lane >> 2;
        const int cq = (lane & 3) * 2;
        #pragma unroll
        for (int mt = 0; mt < 2; ++mt)
            #pragma unroll
            for (int nt = 0; nt < 2; ++nt) {
                const int rr = mt * 16 + r;
                const int cc = wrp * 16 + nt * 8 + cq;
                Z[rr * 68 + cc]           = acc[mt][nt][0];
                Z[rr * 68 + cc + 1]       = acc[mt][nt][1];
                Z[(rr + 8) * 68 + cc]     = acc[mt][nt][2];
                Z[(rr + 8) * 68 + cc + 1] = acc[mt][nt][3];
            }
    }
    __syncthreads();

    // --- Gate math + state update + output write. 512 outputs / 128 threads.
    float* __restrict__ hdst = g_h[(t + 1) & 1];
    #pragma unroll
    for (int i = 0; i < 4; ++i) {
        const int flat = i * 128 + tid;
        const int row = flat >> 4;          // 0..31
        const int jj  = flat & 15;          // 0..15
        const int b = brow0 + row;
        const int j = j0 + jj;
        const int bj = b * H_SZ + j;
        const float zf = Z[row * 68 + jj]      + g_gates[0 * (B_SZ * H_SZ) + bj];
        const float zi = Z[row * 68 + 16 + jj] + g_gates[1 * (B_SZ * H_SZ) + bj];
        const float zo = Z[row * 68 + 32 + jj] + g_gates[2 * (B_SZ * H_SZ) + bj];
        const float zc = Z[row * 68 + 48 + jj] + g_gates[3 * (B_SZ * H_SZ) + bj];
        const float fg = 1.0f / (1.0f + expf(-zf));
        const float ig = 1.0f / (1.0f + expf(-zi));
        const float og = 1.0f / (1.0f + expf(-zo));
        const float ch = tanhf(zc);
        const float cn = fg * g_c[bj] + ig * ch;
        const float hn = og * tanhf(cn);
        g_c[bj] = cn;
        hdst[bj] = hn;
        out[(b * T_SZ + t) * H_SZ + j] = hn;
    }
}

// ---------------------------------------------------------------------------
extern "C" void kernel_launch(void* const* d_in, const int* in_sizes, int n_in,
                              void* d_out, int out_size) {
    (void)in_sizes; (void)n_in; (void)out_size;
    const float* x  = (const float*)d_in[0];
    const float* wf = (const float*)d_in[1];
    const float* wi = (const float*)d_in[2];
    const float* wo = (const float*)d_in[3];
    const float* wc = (const float*)d_in[4];
    const float* uf = (const float*)d_in[5];
    const float* ui = (const float*)d_in[6];
    const float* uo = (const float*)d_in[7];
    const float* uc = (const float*)d_in[8];
    const float* bf = (const float*)d_in[9];
    const float* bi = (const float*)d_in[10];
    const float* bo = (const float*)d_in[11];
    const float* bc = (const float*)d_in[12];
    float* out = (float*)d_out;

    lstm_zero_kernel<<<(B_SZ * H_SZ + 255) / 256, 256>>>();
    lstm_init_gates<<<dim3(H_SZ / 256, B_SZ / 8, 4), 256>>>(
        x, wf, wi, wo, wc, bf, bi, bo, bc);
    for (int t = 0; t < T_SZ; ++t) {
        lstm_step_kernel<<<dim3(H_SZ / 16, 2), 128>>>(uf, ui, uo, uc, out, t);
    }
}

// round 7
// speedup vs baseline: 1.3999x; 1.3892x over previous
#include <cuda_runtime.h>
#include <cstdint>
#include <math.h>

// ---------------------------------------------------------------------------
// EZLSTM on GB300 (sm_103a) — persistent-kernel version.
//
//   g = x[:,0,:] @ W + b                (one-time init kernel, fp32)
//   persistent kernel, 128 CTAs (1/SM), 512 steps inside ONE launch:
//     each CTA owns hidden cols j0..j0+7 for all 4 gates (logical N=32),
//     all 64 batch rows (M=64), K=1024.
//     U weights live in SMEM for the whole kernel (tf32, fragment-ordered).
//     z = h @ U via mma.sync tf32 (fp32 accum); gates/c/h epilogue local.
//     grid-wide barrier (monotone atomic counter) once per step.
// ---------------------------------------------------------------------------

#define B_SZ 64
#define T_SZ 512
#define D_SZ 1024
#define H_SZ 1024

#define GRID    128            // CTAs; <= 148 SMs -> all co-resident (1 CTA/SM)
#define NTHR    256            // 8 warps
#define KCH     64             // K per smem stage
#define NCH     (H_SZ / KCH)   // 16 chunks
#define A_STR   68             // 68 % 32 == 4 -> conflict-free 4r+kq lds pattern

// smem layout (floats)
#define OFF_W   0              // 128*4*32*2 = 32768 : U fragments (tf32 bits)
#define OFF_A   32768          // 2 * 64 * 68 = 8704 : h tile double buffer
#define OFF_Z   41472          // 64 * 33 = 2112     : z staging
#define OFF_G   43584          // 4*64*8 = 2048      : input-gate cache
#define OFF_C   45632          // 64*8 = 512         : cell state
#define SMEM_FLOATS 46144
#define SMEM_BYTES (SMEM_FLOATS * 4)   // 184576 B < 227 KB

// persistent scratch
__device__ float    g_gates[4 * B_SZ * H_SZ];
__device__ float    g_h[2][B_SZ * H_SZ];
__device__ unsigned g_bar;

__device__ __forceinline__ uint32_t f2tf32(float f) {
    // round-to-nearest tf32; truncation bias would compound over K=1024.
    uint32_t r;
    asm("cvt.rna.tf32.f32 %0, %1;" : "=r"(r) : "f"(f));
    return r;
}
__device__ __forceinline__ float4 ldcg_f4(const float* p) {
    float4 v;
    asm volatile("ld.global.cg.v4.f32 {%0,%1,%2,%3}, [%4];"
                 : "=f"(v.x), "=f"(v.y), "=f"(v.z), "=f"(v.w) : "l"(p));
    return v;
}
__device__ __forceinline__ void stcg_f32(float* p, float v) {
    asm volatile("st.global.cg.f32 [%0], %1;" :: "l"(p), "f"(v));
}
__device__ __forceinline__ unsigned ldcg_u32(const unsigned* p) {
    unsigned v;
    asm volatile("ld.global.cg.u32 %0, [%1];" : "=r"(v) : "l"(p));
    return v;
}

// ---------------------------------------------------------------------------
__global__ void lstm_zero_kernel() {
    int i = blockIdx.x * blockDim.x + threadIdx.x;
    if (i == 0) g_bar = 0u;
    if (i < B_SZ * H_SZ) g_h[0][i] = 0.0f;
}

// ---------------------------------------------------------------------------
// g[gate] = x0 @ W_gate + b_gate (one-time, fp32)
__global__ void lstm_init_gates(const float* __restrict__ x,
    const float* __restrict__ wf, const float* __restrict__ wi,
    const float* __restrict__ wo, const float* __restrict__ wc,
    const float* __restrict__ bf, const float* __restrict__ bi,
    const float* __restrict__ bo, const float* __restrict__ bc)
{
    const int gate = blockIdx.z;
    const int bg = blockIdx.y;
    const int j = blockIdx.x * blockDim.x + threadIdx.x;
    const float* w  = (gate == 0) ? wf : (gate == 1) ? wi : (gate == 2) ? wo : wc;
    const float* bb = (gate == 0) ? bf : (gate == 1) ? bi : (gate == 2) ? bo : bc;

    float acc[8];
    #pragma unroll
    for (int r = 0; r < 8; ++r) acc[r] = bb[j];
    for (int d = 0; d < D_SZ; ++d) {
        const float wv = w[d * H_SZ + j];
        #pragma unroll
        for (int r = 0; r < 8; ++r)
            acc[r] = fmaf(x[(bg * 8 + r) * (T_SZ * D_SZ) + d], wv, acc[r]);
    }
    #pragma unroll
    for (int r = 0; r < 8; ++r)
        g_gates[gate * (B_SZ * H_SZ) + (bg * 8 + r) * H_SZ + j] = acc[r];
}

// ---------------------------------------------------------------------------
__global__ void __launch_bounds__(NTHR, 1) lstm_persistent(
    const float* __restrict__ uf, const float* __restrict__ ui,
    const float* __restrict__ uo, const float* __restrict__ uc,
    float* __restrict__ out)
{
    extern __shared__ float sm[];
    float* sW = sm + OFF_W;
    float* sA = sm + OFF_A;
    float* sZ = sm + OFF_Z;
    float* sG = sm + OFF_G;
    float* sC = sm + OFF_C;

    const int tid  = threadIdx.x;
    const int lane = tid & 31;
    const int wrp  = tid >> 5;
    const int mt   = wrp & 3;        // m16 tile (rows mt*16..+15)
    const int np   = wrp >> 2;       // n-pair: ntiles {2np, 2np+1}
    const int j0   = blockIdx.x * 8; // this CTA's 8 hidden columns

    // ---- one-time: pack U into SMEM, mma-B-fragment order, tf32 bits.
    // fragment slot for (s=k/8, gate): lane l holds (k0+l%4, n=l/4) and (+4).
    #pragma unroll
    for (int gate = 0; gate < 4; ++gate) {
        const float* u = (gate == 0) ? uf : (gate == 1) ? ui
                       : (gate == 2) ? uo : uc;
        for (int idx = tid; idx < 8192; idx += NTHR) {
            const int k = idx >> 3, j = idx & 7;
            const float v = u[k * H_SZ + j0 + j];
            const int s = k >> 3, c = k & 7, half = c >> 2, kq = c & 3;
            const int l = j * 4 + kq;
            sW[((((s * 4 + gate) * 32) + l) << 1) + half] =
                __uint_as_float(f2tf32(v));
        }
    }
    // input-gate cache: sG[gate*512 + b*8 + j]
    for (int idx = tid; idx < 2048; idx += NTHR) {
        const int gate = idx >> 9, rem = idx & 511;
        const int b = rem >> 3, j = rem & 7;
        sG[idx] = g_gates[gate * (B_SZ * H_SZ) + b * H_SZ + j0 + j];
    }
    for (int idx = tid; idx < 512; idx += NTHR) sC[idx] = 0.0f;
    __syncthreads();

    float4 ar[4];   // staged h chunk: 64 rows x 64 k = 1024 float4 / 256 thr

    // ---- 512 recurrent steps
    for (int t = 0; t < T_SZ; ++t) {
        const float* __restrict__ hsrc = g_h[t & 1];
        float* __restrict__ hdst = g_h[(t + 1) & 1];

        float acc[2][4];
        #pragma unroll
        for (int n = 0; n < 2; ++n)
            #pragma unroll
            for (int q = 0; q < 4; ++q) acc[n][q] = 0.0f;

        // prologue: load + store chunk 0
        #pragma unroll
        for (int q = 0; q < 4; ++q) {
            const int f = tid + NTHR * q;
            ar[q] = ldcg_f4(&hsrc[(f >> 4) * H_SZ + ((f & 15) << 2)]);
        }
        {
            float* A = sA;
            #pragma unroll
            for (int q = 0; q < 4; ++q) {
                const int f = tid + NTHR * q;
                float4 v;
                v.x = __uint_as_float(f2tf32(ar[q].x));
                v.y = __uint_as_float(f2tf32(ar[q].y));
                v.z = __uint_as_float(f2tf32(ar[q].z));
                v.w = __uint_as_float(f2tf32(ar[q].w));
                *reinterpret_cast<float4*>(&A[(f >> 4) * A_STR + ((f & 15) << 2)]) = v;
            }
        }

        for (int kc = 0; kc < NCH; ++kc) {
            if (kc + 1 < NCH) {       // prefetch next chunk (L2 latency hides
                #pragma unroll        // behind barrier + compute below)
                for (int q = 0; q < 4; ++q) {
                    const int f = tid + NTHR * q;
                    ar[q] = ldcg_f4(&hsrc[(f >> 4) * H_SZ + (kc + 1) * KCH
                                          + ((f & 15) << 2)]);
                }
            }
            __syncthreads();

            // compute chunk kc from buffer kc&1
            {
                const float* A = sA + (kc & 1) * (64 * A_STR);
                const int r = lane >> 2, kq = lane & 3;
                #pragma unroll
                for (int s = 0; s < 8; ++s) {
                    const int k0 = s * 8;
                    const uint32_t a0 = __float_as_uint(A[(mt * 16 + r)     * A_STR + k0 + kq]);
                    const uint32_t a1 = __float_as_uint(A[(mt * 16 + r + 8) * A_STR + k0 + kq]);
                    const uint32_t a2 = __float_as_uint(A[(mt * 16 + r)     * A_STR + k0 + kq + 4]);
                    const uint32_t a3 = __float_as_uint(A[(mt * 16 + r + 8) * A_STR + k0 + kq + 4]);
                    const int sg = kc * 8 + s;
                    #pragma unroll
                    for (int n = 0; n < 2; ++n) {
                        const int nt = np * 2 + n;
                        const float2 bv = *reinterpret_cast<const float2*>(
                            &sW[(((sg * 4 + nt) * 32) + lane) << 1]);
                        asm volatile(
                            "mma.sync.aligned.m16n8k8.row.col.f32.tf32.tf32.f32 "
                            "{%0,%1,%2,%3},{%4,%5,%6,%7},{%8,%9},{%0,%1,%2,%3};\n"
                            : "+f"(acc[n][0]), "+f"(acc[n][1]),
                              "+f"(acc[n][2]), "+f"(acc[n][3])
                            : "r"(a0), "r"(a1), "r"(a2), "r"(a3),
                              "r"(__float_as_uint(bv.x)),
                              "r"(__float_as_uint(bv.y)));
                    }
                }
            }

            if (kc + 1 < NCH) {       // stage next chunk into the other buffer
                float* A = sA + ((kc + 1) & 1) * (64 * A_STR);
                #pragma unroll
                for (int q = 0; q < 4; ++q) {
                    const int f = tid + NTHR * q;
                    float4 v;
                    v.x = __uint_as_float(f2tf32(ar[q].x));
                    v.y = __uint_as_float(f2tf32(ar[q].y));
                    v.z = __uint_as_float(f2tf32(ar[q].z));
                    v.w = __uint_as_float(f2tf32(ar[q].w));
                    *reinterpret_cast<float4*>(&A[(f >> 4) * A_STR + ((f & 15) << 2)]) = v;
                }
            }
        }

        // ---- stage z (64 rows x 32 logical cols) into smem
        {
            const int r = lane >> 2, cq = (lane & 3) * 2;
            #pragma unroll
            for (int n = 0; n < 2; ++n) {
                const int ncol = (np * 2 + n) * 8 + cq;
                const int rr = mt * 16 + r;
                sZ[rr * 33 + ncol]           = acc[n][0];
                sZ[rr * 33 + ncol + 1]       = acc[n][1];
                sZ[(rr + 8) * 33 + ncol]     = acc[n][2];
                sZ[(rr + 8) * 33 + ncol + 1] = acc[n][3];
            }
        }
        __syncthreads();

        // ---- gate math + state update: 512 outputs / 256 threads
        #pragma unroll
        for (int e = 0; e < 2; ++e) {
            const int flat = tid + NTHR * e;       // = b*8 + j
            const int b = flat >> 3, j = flat & 7;
            const float zf = sZ[b * 33 + j]      + sG[flat];
            const float zi = sZ[b * 33 + 8 + j]  + sG[512 + flat];
            const float zo = sZ[b * 33 + 16 + j] + sG[1024 + flat];
            const float zc = sZ[b * 33 + 24 + j] + sG[1536 + flat];
            const float fg = 1.0f / (1.0f + expf(-zf));
            const float ig = 1.0f / (1.0f + expf(-zi));
            const float og = 1.0f / (1.0f + expf(-zo));
            const float ch = tanhf(zc);
            const float cn = fg * sC[flat] + ig * ch;
            const float hn = og * tanhf(cn);
            sC[flat] = cn;
            stcg_f32(&hdst[b * H_SZ + j0 + j], hn);
            out[(b * T_SZ + t) * H_SZ + j0 + j] = hn;
        }
        __syncthreads();

        // ---- grid barrier (monotone counter; reset per launch by zero kernel)
        if (tid == 0) {
            __threadfence();
            atomicAdd(&g_bar, 1u);
            const unsigned target = (unsigned)(t + 1) * GRID;
            while (ldcg_u32(&g_bar) < target) __nanosleep(32);
        }
        __syncthreads();
    }
}

// ---------------------------------------------------------------------------
extern "C" void kernel_launch(void* const* d_in, const int* in_sizes, int n_in,
                              void* d_out, int out_size) {
    (void)in_sizes; (void)n_in; (void)out_size;
    const float* x  = (const float*)d_in[0];
    const float* wf = (const float*)d_in[1];
    const float* wi = (const float*)d_in[2];
    const float* wo = (const float*)d_in[3];
    const float* wc = (const float*)d_in[4];
    const float* uf = (const float*)d_in[5];
    const float* ui = (const float*)d_in[6];
    const float* uo = (const float*)d_in[7];
    const float* uc = (const float*)d_in[8];
    const float* bf = (const float*)d_in[9];
    const float* bi = (const float*)d_in[10];
    const float* bo = (const float*)d_in[11];
    const float* bc = (const float*)d_in[12];
    float* out = (float*)d_out;

    cudaFuncSetAttribute(lstm_persistent,
                         cudaFuncAttributeMaxDynamicSharedMemorySize, SMEM_BYTES);

    lstm_zero_kernel<<<(B_SZ * H_SZ + 255) / 256, 256>>>();
    lstm_init_gates<<<dim3(H_SZ / 256, B_SZ / 8, 4), 256>>>(
        x, wf, wi, wo, wc, bf, bi, bo, bc);
    lstm_persistent<<<GRID, NTHR, SMEM_BYTES>>>(uf, ui, uo, uc, out);
}

// round 8
// speedup vs baseline: 2.1631x; 1.5452x over previous
#include <cuda_runtime.h>
#include <cstdint>
#include <math.h>

// ---------------------------------------------------------------------------
// EZLSTM on GB300 (sm_103a) — persistent kernel, h stored as tf32 bits.
//
//   g = x[:,0,:] @ W + b                   (one-time init kernel, fp32)
//   persistent kernel, 128 CTAs (1/SM), 512 steps in ONE launch:
//     CTA owns 8 hidden cols x 4 gates (N=32), all 64 batch rows, K=1024.
//     U weights in SMEM for the whole kernel (tf32, mma-fragment order).
//     h kept in GLOBAL as tf32 bit patterns -> staging is a raw copy
//     (the per-step 64K cvt.rna per SM of the previous version is gone;
//      each h element is converted exactly once, by its producer).
//     z = h @ U via mma.sync tf32 (fp32 accum); grid barrier per step.
// ---------------------------------------------------------------------------

#define B_SZ 64
#define T_SZ 512
#define D_SZ 1024
#define H_SZ 1024

#define GRID    128            // 1 CTA/SM, all co-resident
#define NTHR    256            // 8 warps
#define KCH     128            // K per smem stage
#define NCH     (H_SZ / KCH)   // 8 chunks
#define A_STR   132            // 132 % 32 == 4 -> conflict-free lds pattern

// smem layout (32-bit words)
#define OFF_W   0              // 128*4*32*2 = 32768 : U fragments (tf32 bits)
#define OFF_A   32768          // 2 * 64 * 132 = 16896 : h tile double buffer
#define OFF_Z   49664          // 64 * 33 = 2112     : z staging
#define OFF_G   51776          // 4*64*8 = 2048      : input-gate cache
#define OFF_C   53824          // 64*8 = 512         : cell state
#define SMEM_WORDS 54336
#define SMEM_BYTES (SMEM_WORDS * 4)   // 217344 B < 227 KB

// persistent scratch
__device__ uint32_t g_h[2][B_SZ * H_SZ];     // h as tf32 bit patterns
__device__ float    g_gates[4 * B_SZ * H_SZ];
__device__ unsigned g_bar;

__device__ __forceinline__ uint32_t f2tf32(float f) {
    // round-to-nearest tf32; truncation bias would compound over K=1024.
    uint32_t r;
    asm("cvt.rna.tf32.f32 %0, %1;" : "=r"(r) : "f"(f));
    return r;
}
__device__ __forceinline__ uint4 ldcg_u4(const uint32_t* p) {
    uint4 v;
    asm volatile("ld.global.cg.v4.u32 {%0,%1,%2,%3}, [%4];"
                 : "=r"(v.x), "=r"(v.y), "=r"(v.z), "=r"(v.w) : "l"(p));
    return v;
}
__device__ __forceinline__ void stcg_u32(uint32_t* p, uint32_t v) {
    asm volatile("st.global.cg.u32 [%0], %1;" :: "l"(p), "r"(v));
}
__device__ __forceinline__ unsigned ldcg_u32(const unsigned* p) {
    unsigned v;
    asm volatile("ld.global.cg.u32 %0, [%1];" : "=r"(v) : "l"(p));
    return v;
}

// ---------------------------------------------------------------------------
__global__ void lstm_zero_kernel() {
    int i = blockIdx.x * blockDim.x + threadIdx.x;
    if (i == 0) g_bar = 0u;
    if (i < B_SZ * H_SZ) g_h[0][i] = 0u;      // tf32 bits of 0.0f
}

// ---------------------------------------------------------------------------
// g[gate] = x0 @ W_gate + b_gate (one-time, fp32)
__global__ void lstm_init_gates(const float* __restrict__ x,
    const float* __restrict__ wf, const float* __restrict__ wi,
    const float* __restrict__ wo, const float* __restrict__ wc,
    const float* __restrict__ bf, const float* __restrict__ bi,
    const float* __restrict__ bo, const float* __restrict__ bc)
{
    const int gate = blockIdx.z;
    const int bg = blockIdx.y;
    const int j = blockIdx.x * blockDim.x + threadIdx.x;
    const float* w  = (gate == 0) ? wf : (gate == 1) ? wi : (gate == 2) ? wo : wc;
    const float* bb = (gate == 0) ? bf : (gate == 1) ? bi : (gate == 2) ? bo : bc;

    float acc[8];
    #pragma unroll
    for (int r = 0; r < 8; ++r) acc[r] = bb[j];
    for (int d = 0; d < D_SZ; ++d) {
        const float wv = w[d * H_SZ + j];
        #pragma unroll
        for (int r = 0; r < 8; ++r)
            acc[r] = fmaf(x[(bg * 8 + r) * (T_SZ * D_SZ) + d], wv, acc[r]);
    }
    #pragma unroll
    for (int r = 0; r < 8; ++r)
        g_gates[gate * (B_SZ * H_SZ) + (bg * 8 + r) * H_SZ + j] = acc[r];
}

// ---------------------------------------------------------------------------
__global__ void __launch_bounds__(NTHR, 1) lstm_persistent(
    const float* __restrict__ uf, const float* __restrict__ ui,
    const float* __restrict__ uo, const float* __restrict__ uc,
    float* __restrict__ out)
{
    extern __shared__ uint32_t sm[];
    uint32_t* sW = sm + OFF_W;
    uint32_t* sA = sm + OFF_A;
    float*    sZ = reinterpret_cast<float*>(sm + OFF_Z);
    float*    sG = reinterpret_cast<float*>(sm + OFF_G);
    float*    sC = reinterpret_cast<float*>(sm + OFF_C);

    const int tid  = threadIdx.x;
    const int lane = tid & 31;
    const int wrp  = tid >> 5;
    const int mt   = wrp & 3;        // m16 tile (rows mt*16..+15)
    const int np   = wrp >> 2;       // n-pair: ntiles {2np, 2np+1}
    const int j0   = blockIdx.x * 8; // this CTA's 8 hidden columns

    // ---- one-time: pack U into SMEM, mma-B-fragment order, tf32 bits.
    #pragma unroll
    for (int gate = 0; gate < 4; ++gate) {
        const float* u = (gate == 0) ? uf : (gate == 1) ? ui
                       : (gate == 2) ? uo : uc;
        for (int idx = tid; idx < 8192; idx += NTHR) {
            const int k = idx >> 3, j = idx & 7;
            const float v = u[k * H_SZ + j0 + j];
            const int s = k >> 3, c = k & 7, half = c >> 2, kq = c & 3;
            const int l = j * 4 + kq;
            sW[((((s * 4 + gate) * 32) + l) << 1) + half] = f2tf32(v);
        }
    }
    for (int idx = tid; idx < 2048; idx += NTHR) {
        const int gate = idx >> 9, rem = idx & 511;
        const int b = rem >> 3, j = rem & 7;
        sG[idx] = g_gates[gate * (B_SZ * H_SZ) + b * H_SZ + j0 + j];
    }
    for (int idx = tid; idx < 512; idx += NTHR) sC[idx] = 0.0f;
    __syncthreads();

    uint4 ar[8];    // staged h chunk: 64 rows x 128 k = 2048 uint4 / 256 thr

    // ---- 512 recurrent steps
    for (int t = 0; t < T_SZ; ++t) {
        const uint32_t* __restrict__ hsrc = g_h[t & 1];
        uint32_t* __restrict__ hdst = g_h[(t + 1) & 1];

        float acc[2][4];
        #pragma unroll
        for (int n = 0; n < 2; ++n)
            #pragma unroll
            for (int q = 0; q < 4; ++q) acc[n][q] = 0.0f;

        // prologue: load + store chunk 0 (pure copy — h already tf32)
        #pragma unroll
        for (int q = 0; q < 8; ++q) {
            const int f = tid + NTHR * q;
            ar[q] = ldcg_u4(&hsrc[(f >> 5) * H_SZ + ((f & 31) << 2)]);
        }
        #pragma unroll
        for (int q = 0; q < 8; ++q) {
            const int f = tid + NTHR * q;
            *reinterpret_cast<uint4*>(&sA[(f >> 5) * A_STR + ((f & 31) << 2)]) = ar[q];
        }

        for (int kc = 0; kc < NCH; ++kc) {
            if (kc + 1 < NCH) {       // prefetch next chunk before the barrier
                #pragma unroll
                for (int q = 0; q < 8; ++q) {
                    const int f = tid + NTHR * q;
                    ar[q] = ldcg_u4(&hsrc[(f >> 5) * H_SZ + (kc + 1) * KCH
                                          + ((f & 31) << 2)]);
                }
            }
            __syncthreads();

            // compute chunk kc from buffer kc&1
            {
                const uint32_t* A = sA + (kc & 1) * (64 * A_STR);
                const int r = lane >> 2, kq = lane & 3;
                #pragma unroll
                for (int s = 0; s < KCH / 8; ++s) {
                    const int k0 = s * 8;
                    const uint32_t a0 = A[(mt * 16 + r)     * A_STR + k0 + kq];
                    const uint32_t a1 = A[(mt * 16 + r + 8) * A_STR + k0 + kq];
                    const uint32_t a2 = A[(mt * 16 + r)     * A_STR + k0 + kq + 4];
                    const uint32_t a3 = A[(mt * 16 + r + 8) * A_STR + k0 + kq + 4];
                    const int sg = kc * (KCH / 8) + s;
                    #pragma unroll
                    for (int n = 0; n < 2; ++n) {
                        const int nt = np * 2 + n;
                        const uint2 bv = *reinterpret_cast<const uint2*>(
                            &sW[(((sg * 4 + nt) * 32) + lane) << 1]);
                        asm volatile(
                            "mma.sync.aligned.m16n8k8.row.col.f32.tf32.tf32.f32 "
                            "{%0,%1,%2,%3},{%4,%5,%6,%7},{%8,%9},{%0,%1,%2,%3};\n"
                            : "+f"(acc[n][0]), "+f"(acc[n][1]),
                              "+f"(acc[n][2]), "+f"(acc[n][3])
                            : "r"(a0), "r"(a1), "r"(a2), "r"(a3),
                              "r"(bv.x), "r"(bv.y));
                    }
                }
            }

            if (kc + 1 < NCH) {       // stage next chunk into the other buffer
                uint32_t* A = sA + ((kc + 1) & 1) * (64 * A_STR);
                #pragma unroll
                for (int q = 0; q < 8; ++q) {
                    const int f = tid + NTHR * q;
                    *reinterpret_cast<uint4*>(
                        &A[(f >> 5) * A_STR + ((f & 31) << 2)]) = ar[q];
                }
            }
        }

        // ---- stage z (64 rows x 32 logical cols) into smem
        {
            const int r = lane >> 2, cq = (lane & 3) * 2;
            #pragma unroll
            for (int n = 0; n < 2; ++n) {
                const int ncol = (np * 2 + n) * 8 + cq;
                const int rr = mt * 16 + r;
                sZ[rr * 33 + ncol]           = acc[n][0];
                sZ[rr * 33 + ncol + 1]       = acc[n][1];
                sZ[(rr + 8) * 33 + ncol]     = acc[n][2];
                sZ[(rr + 8) * 33 + ncol + 1] = acc[n][3];
            }
        }
        __syncthreads();

        // ---- gate math + state update: 512 outputs / 256 threads
        #pragma unroll
        for (int e = 0; e < 2; ++e) {
            const int flat = tid + NTHR * e;       // = b*8 + j
            const int b = flat >> 3, j = flat & 7;
            const float zf = sZ[b * 33 + j]      + sG[flat];
            const float zi = sZ[b * 33 + 8 + j]  + sG[512 + flat];
            const float zo = sZ[b * 33 + 16 + j] + sG[1024 + flat];
            const float zc = sZ[b * 33 + 24 + j] + sG[1536 + flat];
            const float fg = 1.0f / (1.0f + expf(-zf));
            const float ig = 1.0f / (1.0f + expf(-zi));
            const float og = 1.0f / (1.0f + expf(-zo));
            const float ch = tanhf(zc);
            const float cn = fg * sC[flat] + ig * ch;
            const float hn = og * tanhf(cn);
            sC[flat] = cn;
            stcg_u32(&hdst[b * H_SZ + j0 + j], f2tf32(hn));  // converted ONCE
            out[(b * T_SZ + t) * H_SZ + j0 + j] = hn;
        }
        __syncthreads();

        // ---- grid barrier (monotone counter; reset each launch by zero kernel)
        if (tid == 0) {
            __threadfence();
            atomicAdd(&g_bar, 1u);
            const unsigned target = (unsigned)(t + 1) * GRID;
            while (ldcg_u32(&g_bar) < target) __nanosleep(32);
        }
        __syncthreads();
    }
}

// ---------------------------------------------------------------------------
extern "C" void kernel_launch(void* const* d_in, const int* in_sizes, int n_in,
                              void* d_out, int out_size) {
    (void)in_sizes; (void)n_in; (void)out_size;
    const float* x  = (const float*)d_in[0];
    const float* wf = (const float*)d_in[1];
    const float* wi = (const float*)d_in[2];
    const float* wo = (const float*)d_in[3];
    const float* wc = (const float*)d_in[4];
    const float* uf = (const float*)d_in[5];
    const float* ui = (const float*)d_in[6];
    const float* uo = (const float*)d_in[7];
    const float* uc = (const float*)d_in[8];
    const float* bf = (const float*)d_in[9];
    const float* bi = (const float*)d_in[10];
    const float* bo = (const float*)d_in[11];
    const float* bc = (const float*)d_in[12];
    float* out = (float*)d_out;

    cudaFuncSetAttribute(lstm_persistent,
                         cudaFuncAttributeMaxDynamicSharedMemorySize, SMEM_BYTES);

    lstm_zero_kernel<<<(B_SZ * H_SZ + 255) / 256, 256>>>();
    lstm_init_gates<<<dim3(H_SZ / 256, B_SZ / 8, 4), 256>>>(
        x, wf, wi, wo, wc, bf, bi, bo, bc);
    lstm_persistent<<<GRID, NTHR, SMEM_BYTES>>>(uf, ui, uo, uc, out);
}